// round 7
// baseline (speedup 1.0000x reference)
#include <cuda_runtime.h>
#include <cuda_fp16.h>
#include <cstdint>
#include <cstddef>

// Problem dims
#define M_DIM 4096   // batch
#define N_DIM 2048   // out features
#define K_DIM 2048   // in features

// ---------------------------------------------------------------------------
// Scratch (static device arrays — allowed):
//   xhi/whi : fp16 leading part (11 mantissa bits)
//   *hi8    : int8 quantization of hi   (scale 127/8   = 15.875)
//   *lo8    : int8 quantization of lo   (scale 127*512 = 65024; lo <= 2^-9)
// x*w = xhi*whi  +  [xlo*whi + xhi*wlo]/ (15.875*65024)  (+ ~2^-22 dropped)
// ---------------------------------------------------------------------------
__device__ __align__(16) __half g_xhi[(size_t)M_DIM * K_DIM];
__device__ __align__(16) __half g_whi[(size_t)N_DIM * K_DIM];
__device__ __align__(16) int8_t g_xhi8[(size_t)M_DIM * K_DIM];
__device__ __align__(16) int8_t g_xlo8[(size_t)M_DIM * K_DIM];
__device__ __align__(16) int8_t g_whi8[(size_t)N_DIM * K_DIM];
__device__ __align__(16) int8_t g_wlo8[(size_t)N_DIM * K_DIM];

static constexpr float SC_HI  = 15.875f;     // 127/8
static constexpr float SC_LO  = 65024.0f;    // 127*512
static constexpr float INV_SC = 1.0f / 1032256.0f;   // 1/(SC_HI*SC_LO)

// ---------------------------------------------------------------------------
// Helpers (baseline sm_103 ISA: cp.async, ldmatrix, mma.sync f16 + s8)
// ---------------------------------------------------------------------------
__device__ __forceinline__ uint32_t smem_u32(const void* p) {
    uint32_t a;
    asm("{ .reg .u64 t; cvta.to.shared.u64 t, %1; cvt.u32.u64 %0, t; }"
        : "=r"(a) : "l"(p));
    return a;
}

__device__ __forceinline__ void cp_async16(uint32_t saddr, const void* gaddr) {
    asm volatile("cp.async.cg.shared.global [%0], [%1], 16;"
                 :: "r"(saddr), "l"(gaddr) : "memory");
}

__device__ __forceinline__ void ldsm4(uint32_t* r, uint32_t addr) {
    asm volatile("ldmatrix.sync.aligned.m8n8.x4.shared.b16 {%0,%1,%2,%3}, [%4];"
                 : "=r"(r[0]), "=r"(r[1]), "=r"(r[2]), "=r"(r[3])
                 : "r"(addr));
}

__device__ __forceinline__ void mma_f16(float* d, const uint32_t* a,
                                        const uint32_t b0, const uint32_t b1) {
    asm volatile(
        "mma.sync.aligned.m16n8k16.row.col.f32.f16.f16.f32 "
        "{%0,%1,%2,%3}, {%4,%5,%6,%7}, {%8,%9}, {%0,%1,%2,%3};"
        : "+f"(d[0]), "+f"(d[1]), "+f"(d[2]), "+f"(d[3])
        : "r"(a[0]), "r"(a[1]), "r"(a[2]), "r"(a[3]), "r"(b0), "r"(b1));
}

__device__ __forceinline__ void mma_s8(int* d, const uint32_t* a,
                                       const uint32_t b0, const uint32_t b1) {
    asm volatile(
        "mma.sync.aligned.m16n8k32.row.col.s32.s8.s8.s32 "
        "{%0,%1,%2,%3}, {%4,%5,%6,%7}, {%8,%9}, {%0,%1,%2,%3};"
        : "+r"(d[0]), "+r"(d[1]), "+r"(d[2]), "+r"(d[3])
        : "r"(a[0]), "r"(a[1]), "r"(a[2]), "r"(a[3]), "r"(b0), "r"(b1));
}

// ---------------------------------------------------------------------------
// Split kernels: fp32 -> fp16 hi + int8(hi) + int8(lo*512).  8 elems/thread.
// ---------------------------------------------------------------------------
union H8 { __half h[8]; uint4 u; };
union B8 { int8_t c[8]; uint2 u; };

__device__ __forceinline__ void split8(const float* __restrict__ src, size_t base,
                                       __half* hi, int8_t* hi8, int8_t* lo8) {
    float4 a = *reinterpret_cast<const float4*>(src + base);
    float4 b = *reinterpret_cast<const float4*>(src + base + 4);
    float f[8] = {a.x, a.y, a.z, a.w, b.x, b.y, b.z, b.w};
    H8 H; B8 Hi, Lo;
#pragma unroll
    for (int j = 0; j < 8; j++) {
        __half h = __float2half_rn(f[j]);
        float hf = __half2float(h);
        float lo = f[j] - hf;
        int vh = __float2int_rn(hf * SC_HI);
        int vl = __float2int_rn(lo * SC_LO);
        vh = max(-127, min(127, vh));
        vl = max(-127, min(127, vl));
        H.h[j]  = h;
        Hi.c[j] = (int8_t)vh;
        Lo.c[j] = (int8_t)vl;
    }
    *reinterpret_cast<uint4*>(hi + base)  = H.u;
    *reinterpret_cast<uint2*>(hi8 + base) = Hi.u;
    *reinterpret_cast<uint2*>(lo8 + base) = Lo.u;
}

__global__ void __launch_bounds__(256) split_x_kernel(const float* __restrict__ x) {
    size_t i = (size_t)blockIdx.x * blockDim.x + threadIdx.x;
    if (i * 8 < (size_t)M_DIM * K_DIM)
        split8(x, i * 8, g_xhi, g_xhi8, g_xlo8);
}

__global__ void __launch_bounds__(256) split_w_kernel(const float* __restrict__ w) {
    size_t i = (size_t)blockIdx.x * blockDim.x + threadIdx.x;
    if (i * 8 < (size_t)N_DIM * K_DIM)
        split8(w, i * 8, g_whi, g_whi8, g_wlo8);
}

// ---------------------------------------------------------------------------
// GEMM: 128x128 CTA tile. Per K=32 chunk:
//   fp16 HMMA:  xhi*whi              (2 k16 slices)
//   s8   IMMA:  xlo8*whi8 + xhi8*wlo8 (k32, shared s32 accumulator)
// 8 warps as 4(m) x 2(n), warp tile 32x64. 4-stage cp.async pipeline.
// ---------------------------------------------------------------------------
static constexpr int BK      = 32;
static constexpr int KT      = K_DIM / BK;       // 64
static constexpr int ROW16   = 80;               // 64B data + 16B pad
static constexpr int ROW8    = 48;               // 32B data + 16B pad
static constexpr int T16     = 128 * ROW16;      // 10240
static constexpr int T8      = 128 * ROW8;       // 6144
static constexpr int OFF_XHI16 = 0;
static constexpr int OFF_WHI16 = T16;
static constexpr int OFF_XHI8  = 2 * T16;
static constexpr int OFF_XLO8  = 2 * T16 + T8;
static constexpr int OFF_WHI8  = 2 * T16 + 2 * T8;
static constexpr int OFF_WLO8  = 2 * T16 + 3 * T8;
static constexpr int STAGE_B   = 2 * T16 + 4 * T8;          // 45056
static constexpr int SMEM_DYN  = 4 * STAGE_B + 1024;        // ~177 KB

__global__ void __launch_bounds__(256, 1)
gemm_kernel(const float* __restrict__ bias, float* __restrict__ out) {
    extern __shared__ char smem_raw[];
    const uint32_t dynbase = (smem_u32(smem_raw) + 1023u) & ~1023u;

    const int tid = threadIdx.x;
    const int wid = tid >> 5;
    const int lid = tid & 31;
    const int bn  = blockIdx.x;        // 0..15
    const int bm  = blockIdx.y;        // 0..31

    const int m0 = (wid & 3) * 32;     // warp m-offset
    const int n0 = (wid >> 2) * 64;    // warp n-offset

    const __half*  xhi  = g_xhi  + (size_t)bm * 128 * K_DIM;
    const __half*  whi  = g_whi  + (size_t)bn * 128 * K_DIM;
    const int8_t*  xhi8 = g_xhi8 + (size_t)bm * 128 * K_DIM;
    const int8_t*  xlo8 = g_xlo8 + (size_t)bm * 128 * K_DIM;
    const int8_t*  whi8 = g_whi8 + (size_t)bn * 128 * K_DIM;
    const int8_t*  wlo8 = g_wlo8 + (size_t)bn * 128 * K_DIM;

    // cp.async geometry.
    // fp16 tiles: 512 chunks of 16B (row=c/4, col16=c%4), 2 per thread.
    // int8 tiles: 256 chunks of 16B (row=c/2, col16=c%2), 1 per thread.
    const int r16[2] = {tid >> 2, (tid + 256) >> 2};
    const int c16[2] = {tid & 3, (tid + 256) & 3};
    const int r8 = tid >> 1, c8 = tid & 1;

    auto load_stage = [&](int s, int kt) {
        const int k0 = kt * BK;
        const uint32_t sb = dynbase + s * STAGE_B;
#pragma unroll
        for (int h = 0; h < 2; h++) {
            const uint32_t so = (uint32_t)(r16[h] * ROW16 + c16[h] * 16);
            const size_t  go = (size_t)r16[h] * K_DIM + k0 + c16[h] * 8;
            cp_async16(sb + OFF_XHI16 + so, xhi + go);
            cp_async16(sb + OFF_WHI16 + so, whi + go);
        }
        {
            const uint32_t so = (uint32_t)(r8 * ROW8 + c8 * 16);
            const size_t  go = (size_t)r8 * K_DIM + k0 + c8 * 16;
            cp_async16(sb + OFF_XHI8 + so, xhi8 + go);
            cp_async16(sb + OFF_XLO8 + so, xlo8 + go);
            cp_async16(sb + OFF_WHI8 + so, whi8 + go);
            cp_async16(sb + OFF_WLO8 + so, wlo8 + go);
        }
        asm volatile("cp.async.commit_group;" ::: "memory");
    };

    // ldmatrix per-lane base offsets: lane l -> row l%16, 16B chunk l/16.
    const uint32_t lrow = (uint32_t)(lid & 15);
    const uint32_t lchk = (uint32_t)(lid >> 4) * 16;
    const uint32_t aoff16 = (uint32_t)(m0 + lrow) * ROW16 + lchk;
    const uint32_t boff16 = (uint32_t)(n0 + lrow) * ROW16 + lchk;
    const uint32_t aoff8  = (uint32_t)(m0 + lrow) * ROW8  + lchk;
    const uint32_t boff8  = (uint32_t)(n0 + lrow) * ROW8  + lchk;

    float acc_f[2][8][4];
    int   acc_i[2][8][4];
#pragma unroll
    for (int mt = 0; mt < 2; mt++)
#pragma unroll
        for (int nt = 0; nt < 8; nt++)
#pragma unroll
            for (int q = 0; q < 4; q++) { acc_f[mt][nt][q] = 0.0f; acc_i[mt][nt][q] = 0; }

    // Prologue: fill 3 stages
    load_stage(0, 0);
    load_stage(1, 1);
    load_stage(2, 2);

#pragma unroll 1
    for (int kt = 0; kt < KT; kt++) {
        asm volatile("cp.async.wait_group 2;" ::: "memory");
        __syncthreads();

        if (kt + 3 < KT) load_stage((kt + 3) & 3, kt + 3);
        else asm volatile("cp.async.commit_group;" ::: "memory");

        const uint32_t sb = dynbase + (kt & 3) * STAGE_B;

        // ---- fp16 hi*hi : 2 slices of K=16 ----
#pragma unroll
        for (int ks = 0; ks < 2; ks++) {
            const uint32_t kb = (uint32_t)(ks * 32);   // 16 halves = 32B
            uint32_t A[2][4];
#pragma unroll
            for (int mt = 0; mt < 2; mt++)
                ldsm4(A[mt], sb + OFF_XHI16 + aoff16 + mt * (16 * ROW16) + kb);
#pragma unroll
            for (int nt2 = 0; nt2 < 4; nt2++) {
                uint32_t r[4];
                ldsm4(r, sb + OFF_WHI16 + boff16 + nt2 * (16 * ROW16) + kb);
#pragma unroll
                for (int mt = 0; mt < 2; mt++) {
                    mma_f16(acc_f[mt][nt2 * 2],     A[mt], r[0], r[2]);
                    mma_f16(acc_f[mt][nt2 * 2 + 1], A[mt], r[1], r[3]);
                }
            }
        }

        // ---- int8 corrections : K=32 in one IMMA slice ----
        {
            uint32_t Xl[2][4], Xh[2][4];
#pragma unroll
            for (int mt = 0; mt < 2; mt++) {
                ldsm4(Xl[mt], sb + OFF_XLO8 + aoff8 + mt * (16 * ROW8));
                ldsm4(Xh[mt], sb + OFF_XHI8 + aoff8 + mt * (16 * ROW8));
            }
#pragma unroll
            for (int q = 0; q < 4; q++) {            // q covers n-rows q*16..+15
                uint32_t rb[4], rc[4];
                ldsm4(rb, sb + OFF_WHI8 + boff8 + q * (16 * ROW8));
                ldsm4(rc, sb + OFF_WLO8 + boff8 + q * (16 * ROW8));
#pragma unroll
                for (int mt = 0; mt < 2; mt++) {
                    mma_s8(acc_i[mt][q * 2],     Xl[mt], rb[0], rb[2]);  // xlo*whi
                    mma_s8(acc_i[mt][q * 2],     Xh[mt], rc[0], rc[2]);  // xhi*wlo
                    mma_s8(acc_i[mt][q * 2 + 1], Xl[mt], rb[1], rb[3]);
                    mma_s8(acc_i[mt][q * 2 + 1], Xh[mt], rc[1], rc[3]);
                }
            }
        }
    }

    // Epilogue: out = acc_f + acc_i/ (SC_HI*SC_LO) + bias
    const int cq = (lid & 3) * 2;
    const int cr = lid >> 2;
    const float* bp = bias + bn * 128 + n0;

    float2 bv[8];
#pragma unroll
    for (int nt = 0; nt < 8; nt++)
        bv[nt] = *reinterpret_cast<const float2*>(bp + nt * 8 + cq);

#pragma unroll
    for (int mt = 0; mt < 2; mt++) {
        const int row_g = bm * 128 + m0 + mt * 16 + cr;
        float* orow = out + (size_t)row_g * N_DIM + bn * 128 + n0;
#pragma unroll
        for (int nt = 0; nt < 8; nt++) {
            float2 v0, v1;
            v0.x = acc_f[mt][nt][0] + (float)acc_i[mt][nt][0] * INV_SC + bv[nt].x;
            v0.y = acc_f[mt][nt][1] + (float)acc_i[mt][nt][1] * INV_SC + bv[nt].y;
            v1.x = acc_f[mt][nt][2] + (float)acc_i[mt][nt][2] * INV_SC + bv[nt].x;
            v1.y = acc_f[mt][nt][3] + (float)acc_i[mt][nt][3] * INV_SC + bv[nt].y;
            *reinterpret_cast<float2*>(orow + nt * 8 + cq) = v0;
            *reinterpret_cast<float2*>(orow + (size_t)8 * N_DIM + nt * 8 + cq) = v1;
        }
    }
}

// ---------------------------------------------------------------------------
// kernel_launch
// ---------------------------------------------------------------------------
extern "C" void kernel_launch(void* const* d_in, const int* in_sizes, int n_in,
                              void* d_out, int out_size) {
    const float* x    = (const float*)d_in[0];   // [4096, 2048]
    const float* w    = (const float*)d_in[1];   // [2048, 2048]
    const float* bias = (const float*)d_in[2];   // [2048]
    float* out = (float*)d_out;                  // [4096, 2048]

    (void)in_sizes; (void)n_in; (void)out_size;

    split_x_kernel<<<(M_DIM * K_DIM / 8 + 255) / 256, 256>>>(x);
    split_w_kernel<<<(N_DIM * K_DIM / 8 + 255) / 256, 256>>>(w);

    static bool attr_set = false;
    if (!attr_set) {
        cudaFuncSetAttribute(gemm_kernel,
                             cudaFuncAttributeMaxDynamicSharedMemorySize, SMEM_DYN);
        attr_set = true;
    }
    dim3 grid(N_DIM / 128, M_DIM / 128);   // (16, 32)
    gemm_kernel<<<grid, 256, SMEM_DYN>>>(bias, out);
}

// round 10
// speedup vs baseline: 4.9773x; 4.9773x over previous
#include <cuda_runtime.h>
#include <cuda_fp16.h>
#include <cstdint>
#include <cstddef>

// Problem dims
#define M_DIM 4096   // batch
#define N_DIM 2048   // out features
#define K_DIM 2048   // in features

// ---------------------------------------------------------------------------
// Scratch: fp16 copies of x and w (static device arrays — allowed).
// Single-product fp16 GEMM with fp32 accumulate:
//   per-product rel err ~2^-12 RMS, random signs over K=2048 -> norm rel_err
//   ~2e-4, ~5x under the 1e-3 gate (harness metric is norm-based; round-6
//   measurement matched norm theory at ~1e-5).
// ---------------------------------------------------------------------------
__device__ __align__(16) __half g_xh[(size_t)M_DIM * K_DIM];
__device__ __align__(16) __half g_wh[(size_t)N_DIM * K_DIM];

// ---------------------------------------------------------------------------
// Helpers (baseline sm_103 ISA: cp.async, ldmatrix, mma.sync f16)
// ---------------------------------------------------------------------------
__device__ __forceinline__ uint32_t smem_u32(const void* p) {
    uint32_t a;
    asm("{ .reg .u64 t; cvta.to.shared.u64 t, %1; cvt.u32.u64 %0, t; }"
        : "=r"(a) : "l"(p));
    return a;
}

__device__ __forceinline__ void cp_async16(uint32_t saddr, const void* gaddr) {
    asm volatile("cp.async.cg.shared.global [%0], [%1], 16;"
                 :: "r"(saddr), "l"(gaddr) : "memory");
}

__device__ __forceinline__ void ldsm4(uint32_t* r, uint32_t addr) {
    asm volatile("ldmatrix.sync.aligned.m8n8.x4.shared.b16 {%0,%1,%2,%3}, [%4];"
                 : "=r"(r[0]), "=r"(r[1]), "=r"(r[2]), "=r"(r[3])
                 : "r"(addr));
}

__device__ __forceinline__ void mma_f16(float* d, const uint32_t* a,
                                        const uint32_t b0, const uint32_t b1) {
    asm volatile(
        "mma.sync.aligned.m16n8k16.row.col.f32.f16.f16.f32 "
        "{%0,%1,%2,%3}, {%4,%5,%6,%7}, {%8,%9}, {%0,%1,%2,%3};"
        : "+f"(d[0]), "+f"(d[1]), "+f"(d[2]), "+f"(d[3])
        : "r"(a[0]), "r"(a[1]), "r"(a[2]), "r"(a[3]), "r"(b0), "r"(b1));
}

// ---------------------------------------------------------------------------
// Convert kernels: fp32 -> fp16 (round to nearest), 8 elems/thread
// ---------------------------------------------------------------------------
union H8 { __half h[8]; uint4 u; };

__device__ __forceinline__ void cvt8(const float* __restrict__ src, size_t base,
                                     __half* dst) {
    float4 a = *reinterpret_cast<const float4*>(src + base);
    float4 b = *reinterpret_cast<const float4*>(src + base + 4);
    H8 H;
    H.h[0] = __float2half_rn(a.x); H.h[1] = __float2half_rn(a.y);
    H.h[2] = __float2half_rn(a.z); H.h[3] = __float2half_rn(a.w);
    H.h[4] = __float2half_rn(b.x); H.h[5] = __float2half_rn(b.y);
    H.h[6] = __float2half_rn(b.z); H.h[7] = __float2half_rn(b.w);
    *reinterpret_cast<uint4*>(dst + base) = H.u;
}

__global__ void __launch_bounds__(256) cvt_x_kernel(const float* __restrict__ x) {
    size_t i = (size_t)blockIdx.x * blockDim.x + threadIdx.x;
    if (i * 8 < (size_t)M_DIM * K_DIM) cvt8(x, i * 8, g_xh);
}

__global__ void __launch_bounds__(256) cvt_w_kernel(const float* __restrict__ w) {
    size_t i = (size_t)blockIdx.x * blockDim.x + threadIdx.x;
    if (i * 8 < (size_t)N_DIM * K_DIM) cvt8(w, i * 8, g_wh);
}

// ---------------------------------------------------------------------------
// GEMM: 128x128 CTA tile of out = x @ w^T + bias, single fp16 product,
// fp32 register accumulators. 8 warps as 4(m) x 2(n): warp tile 32x64.
// BK=32, 4-stage cp.async pipeline (same proven structure as the 411us
// round-6 kernel, minus the lo-term tiles -> 1/3 the HMMA count).
// Smem 83 KB -> 2 CTAs/SM for extra latency hiding.
// ---------------------------------------------------------------------------
static constexpr int BK       = 32;                // fp16 elements per K-chunk
static constexpr int KT       = K_DIM / BK;        // 64 iterations
static constexpr int ROW_B    = BK * 2 + 16;       // 80B padded row (conflict-free ldsm)
static constexpr int TILE_B   = 128 * ROW_B;       // 10240 B per 128x32 tile
static constexpr int STAGE_B  = 2 * TILE_B;        // A, B = 20480 B
static constexpr int NSTAGE   = 4;
static constexpr int SMEM_DYN = NSTAGE * STAGE_B + 1024;   // ~83 KB

__global__ void __launch_bounds__(256)
gemm_kernel(const float* __restrict__ bias, float* __restrict__ out) {
    extern __shared__ char smem_raw[];
    const uint32_t dynbase = (smem_u32(smem_raw) + 1023u) & ~1023u;

    const int tid = threadIdx.x;
    const int wid = tid >> 5;
    const int lid = tid & 31;
    const int bn  = blockIdx.x;        // 0..15
    const int bm  = blockIdx.y;        // 0..31

    const int m0 = (wid & 3) * 32;     // warp m-offset in CTA tile
    const int n0 = (wid >> 2) * 64;    // warp n-offset in CTA tile

    const __half* xh = g_xh + (size_t)bm * 128 * K_DIM;
    const __half* wh = g_wh + (size_t)bn * 128 * K_DIM;

    // Per-thread cp.async geometry: 2 chunks of 16B per tile per stage.
    // chunk ci2 in [0,512): row = ci2/4 (0..127), c4 = ci2%4 (16B column).
    int rowi[2], coli[2];
    uint32_t soff[2];
#pragma unroll
    for (int h = 0; h < 2; h++) {
        int ci2 = h * 256 + tid;
        rowi[h] = ci2 >> 2;
        coli[h] = (ci2 & 3) * 8;                         // fp16 elements
        soff[h] = (uint32_t)(rowi[h] * ROW_B + (ci2 & 3) * 16);
    }

    auto load_stage = [&](int s, int kt) {
        const int k0 = kt * BK;
        const uint32_t sb = dynbase + s * STAGE_B;
#pragma unroll
        for (int h = 0; h < 2; h++) {
            const size_t go = (size_t)rowi[h] * K_DIM + k0 + coli[h];
            cp_async16(sb + soff[h],          xh + go);
            cp_async16(sb + TILE_B + soff[h], wh + go);
        }
        asm volatile("cp.async.commit_group;" ::: "memory");
    };

    // ldmatrix per-lane base offsets (bytes) within a tile
    const uint32_t lrow = (uint32_t)(lid & 15);
    const uint32_t lchk = (uint32_t)(lid >> 4) * 16;
    const uint32_t aoff = (uint32_t)(m0 + lrow) * ROW_B + lchk;
    const uint32_t boff = (uint32_t)(n0 + lrow) * ROW_B + lchk;

    float acc[2][8][4];
#pragma unroll
    for (int mt = 0; mt < 2; mt++)
#pragma unroll
        for (int nt = 0; nt < 8; nt++)
#pragma unroll
            for (int q = 0; q < 4; q++) acc[mt][nt][q] = 0.0f;

    // Prologue: fill 3 stages
    load_stage(0, 0);
    load_stage(1, 1);
    load_stage(2, 2);

#pragma unroll 1
    for (int kt = 0; kt < KT; kt++) {
        asm volatile("cp.async.wait_group 2;" ::: "memory");
        __syncthreads();

        // Refill stage (kt+3); its slot was consumed at iter kt-1 (guarded by
        // the barrier above). Always commit so wait_group accounting stays 1:1.
        if (kt + 3 < KT) load_stage((kt + 3) & 3, kt + 3);
        else asm volatile("cp.async.commit_group;" ::: "memory");

        const uint32_t sba = dynbase + (kt & 3) * STAGE_B;
        const uint32_t sbb = sba + TILE_B;

#pragma unroll
        for (int ks = 0; ks < 2; ks++) {
            const uint32_t kb = (uint32_t)(ks * 32);   // 16 halves = 32B

            uint32_t A[2][4];
#pragma unroll
            for (int mt = 0; mt < 2; mt++)
                ldsm4(A[mt], sba + aoff + mt * (16 * ROW_B) + kb);

#pragma unroll
            for (int nt2 = 0; nt2 < 4; nt2++) {
                uint32_t r[4];
                ldsm4(r, sbb + boff + nt2 * (16 * ROW_B) + kb);
#pragma unroll
                for (int mt = 0; mt < 2; mt++) {
                    mma_f16(acc[mt][nt2 * 2],     A[mt], r[0], r[2]);
                    mma_f16(acc[mt][nt2 * 2 + 1], A[mt], r[1], r[3]);
                }
            }
        }
    }

    // Epilogue: add bias, store float2 per fragment half.
    const int cq = (lid & 3) * 2;       // col pair within n8 tile
    const int cr = lid >> 2;            // row within m16 tile (0..7)
    const float* bp = bias + bn * 128 + n0;

    float2 bv[8];
#pragma unroll
    for (int nt = 0; nt < 8; nt++)
        bv[nt] = *reinterpret_cast<const float2*>(bp + nt * 8 + cq);

#pragma unroll
    for (int mt = 0; mt < 2; mt++) {
        const int row_g = bm * 128 + m0 + mt * 16 + cr;
        float* orow = out + (size_t)row_g * N_DIM + bn * 128 + n0;
#pragma unroll
        for (int nt = 0; nt < 8; nt++) {
            float2 v0, v1;
            v0.x = acc[mt][nt][0] + bv[nt].x;
            v0.y = acc[mt][nt][1] + bv[nt].y;
            v1.x = acc[mt][nt][2] + bv[nt].x;
            v1.y = acc[mt][nt][3] + bv[nt].y;
            *reinterpret_cast<float2*>(orow + nt * 8 + cq) = v0;
            *reinterpret_cast<float2*>(orow + (size_t)8 * N_DIM + nt * 8 + cq) = v1;
        }
    }
}

// ---------------------------------------------------------------------------
// kernel_launch: convert x & w to fp16, then single-product HMMA GEMM.
// Graph-capturable (kernel launches only).
// ---------------------------------------------------------------------------
extern "C" void kernel_launch(void* const* d_in, const int* in_sizes, int n_in,
                              void* d_out, int out_size) {
    const float* x    = (const float*)d_in[0];   // [4096, 2048]
    const float* w    = (const float*)d_in[1];   // [2048, 2048]
    const float* bias = (const float*)d_in[2];   // [2048]
    float* out = (float*)d_out;                  // [4096, 2048]

    (void)in_sizes; (void)n_in; (void)out_size;

    cvt_x_kernel<<<(M_DIM * K_DIM / 8 + 255) / 256, 256>>>(x);
    cvt_w_kernel<<<(N_DIM * K_DIM / 8 + 255) / 256, 256>>>(w);

    static bool attr_set = false;
    if (!attr_set) {
        cudaFuncSetAttribute(gemm_kernel,
                             cudaFuncAttributeMaxDynamicSharedMemorySize, SMEM_DYN);
        attr_set = true;
    }
    dim3 grid(N_DIM / 128, M_DIM / 128);   // (16, 32)
    gemm_kernel<<<grid, 256, SMEM_DYN>>>(bias, out);
}

// round 12
// speedup vs baseline: 5.4631x; 1.0976x over previous
#include <cuda_runtime.h>
#include <cuda_fp16.h>
#include <cstdint>
#include <cstddef>

// Problem dims
#define M_DIM 4096   // batch
#define N_DIM 2048   // out features
#define K_DIM 2048   // in features

// ---------------------------------------------------------------------------
// Scratch: fp16 copies of x and w. Single-product fp16 GEMM, fp32 accumulate.
// Measured R10: rel_err 2.94e-4 (gate 1e-3).
// ---------------------------------------------------------------------------
__device__ __align__(16) __half g_xh[(size_t)M_DIM * K_DIM];
__device__ __align__(16) __half g_wh[(size_t)N_DIM * K_DIM];

// ---------------------------------------------------------------------------
// Helpers (baseline sm_103 ISA: cp.async, ldmatrix, mma.sync f16)
// ---------------------------------------------------------------------------
__device__ __forceinline__ uint32_t smem_u32(const void* p) {
    uint32_t a;
    asm("{ .reg .u64 t; cvta.to.shared.u64 t, %1; cvt.u32.u64 %0, t; }"
        : "=r"(a) : "l"(p));
    return a;
}

__device__ __forceinline__ void cp_async16(uint32_t saddr, const void* gaddr) {
    asm volatile("cp.async.cg.shared.global [%0], [%1], 16;"
                 :: "r"(saddr), "l"(gaddr) : "memory");
}

__device__ __forceinline__ void ldsm4(uint32_t* r, uint32_t addr) {
    asm volatile("ldmatrix.sync.aligned.m8n8.x4.shared.b16 {%0,%1,%2,%3}, [%4];"
                 : "=r"(r[0]), "=r"(r[1]), "=r"(r[2]), "=r"(r[3])
                 : "r"(addr));
}

__device__ __forceinline__ void mma_f16(float* d, const uint32_t* a,
                                        const uint32_t b0, const uint32_t b1) {
    asm volatile(
        "mma.sync.aligned.m16n8k16.row.col.f32.f16.f16.f32 "
        "{%0,%1,%2,%3}, {%4,%5,%6,%7}, {%8,%9}, {%0,%1,%2,%3};"
        : "+f"(d[0]), "+f"(d[1]), "+f"(d[2]), "+f"(d[3])
        : "r"(a[0]), "r"(a[1]), "r"(a[2]), "r"(a[3]), "r"(b0), "r"(b1));
}

// ---------------------------------------------------------------------------
// Fused convert kernel: fp32 -> fp16, 16 elems/thread (MLP=4).
// Covers x (first XN elems) then w (next WN). XN divisible by 16, so no
// thread straddles the boundary.
// ---------------------------------------------------------------------------
static constexpr size_t XN = (size_t)M_DIM * K_DIM;          // 8388608
static constexpr size_t WN = (size_t)N_DIM * K_DIM;          // 4194304
static constexpr int CVT_THREADS = (int)((XN + WN) / 16);    // 786432

union H8 { __half h[8]; uint4 u; };

__global__ void __launch_bounds__(256)
cvt_kernel(const float* __restrict__ x, const float* __restrict__ w) {
    size_t t = (size_t)blockIdx.x * blockDim.x + threadIdx.x;
    size_t base = t * 16;
    const float* src;
    __half* dst;
    if (base < XN) { src = x; dst = g_xh; }
    else           { src = w - XN; dst = g_wh - XN; }   // flat offset math

    float4 v[4];
#pragma unroll
    for (int j = 0; j < 4; j++)
        v[j] = *reinterpret_cast<const float4*>(src + base + j * 4);

#pragma unroll
    for (int p = 0; p < 2; p++) {
        H8 H;
        H.h[0] = __float2half_rn(v[p * 2].x);
        H.h[1] = __float2half_rn(v[p * 2].y);
        H.h[2] = __float2half_rn(v[p * 2].z);
        H.h[3] = __float2half_rn(v[p * 2].w);
        H.h[4] = __float2half_rn(v[p * 2 + 1].x);
        H.h[5] = __float2half_rn(v[p * 2 + 1].y);
        H.h[6] = __float2half_rn(v[p * 2 + 1].z);
        H.h[7] = __float2half_rn(v[p * 2 + 1].w);
        *reinterpret_cast<uint4*>(dst + base + p * 8) = H.u;
    }
}

// ---------------------------------------------------------------------------
// GEMM: 128(M) x 64(N) CTA tile, single fp16 product, fp32 accumulators.
// 1024 CTAs -> per-SM max 7 vs avg 6.92 tiles: load imbalance ~1% (was 15.6%
// with 512 CTAs in R10). 8 warps as 4(m) x 2(n): warp tile 32x32 (acc = 32
// regs). BK=32, 4-stage cp.async pipeline. Smem ~62.5 KB, occ 2 pinned.
// ---------------------------------------------------------------------------
static constexpr int BK      = 32;               // fp16 elements per K-chunk
static constexpr int KT      = K_DIM / BK;       // 64 iterations
static constexpr int ROW_B   = BK * 2 + 16;      // 80B padded row (conflict-free ldsm)
static constexpr int TILE_A  = 128 * ROW_B;      // 10240 B (A: 128 rows)
static constexpr int TILE_BB = 64 * ROW_B;       // 5120 B  (B: 64 rows)
static constexpr int STAGE_B = TILE_A + TILE_BB; // 15360 B
static constexpr int NSTAGE  = 4;
static constexpr int SMEM_DYN = NSTAGE * STAGE_B + 1024;   // ~62.5 KB

__global__ void __launch_bounds__(256, 2)
gemm_kernel(const float* __restrict__ bias, float* __restrict__ out) {
    extern __shared__ char smem_raw[];
    const uint32_t dynbase = (smem_u32(smem_raw) + 1023u) & ~1023u;

    const int tid = threadIdx.x;
    const int wid = tid >> 5;
    const int lid = tid & 31;
    const int bn  = blockIdx.x;        // 0..31 (64-wide N tiles)
    const int bm  = blockIdx.y;        // 0..31 (128-high M tiles)

    const int m0 = (wid & 3) * 32;     // warp m-offset in CTA tile
    const int n0 = (wid >> 2) * 32;    // warp n-offset in CTA tile

    const __half* xh = g_xh + (size_t)bm * 128 * K_DIM;
    const __half* wh = g_wh + (size_t)bn * 64 * K_DIM;

    // cp.async geometry:
    //   A tile: 512 chunks of 16B (row=c/4, c4=c%4), 2 per thread.
    //   B tile: 256 chunks of 16B (row=c/4, c4=c%4), 1 per thread.
    int rA[2], cA[2];
    uint32_t sA[2];
#pragma unroll
    for (int h = 0; h < 2; h++) {
        int ci = h * 256 + tid;
        rA[h] = ci >> 2;
        cA[h] = (ci & 3) * 8;
        sA[h] = (uint32_t)(rA[h] * ROW_B + (ci & 3) * 16);
    }
    const int rB = tid >> 2;
    const int cB = (tid & 3) * 8;
    const uint32_t sB = (uint32_t)(rB * ROW_B + (tid & 3) * 16);

    auto load_stage = [&](int s, int kt) {
        const int k0 = kt * BK;
        const uint32_t sb = dynbase + s * STAGE_B;
#pragma unroll
        for (int h = 0; h < 2; h++)
            cp_async16(sb + sA[h], xh + (size_t)rA[h] * K_DIM + k0 + cA[h]);
        cp_async16(sb + TILE_A + sB, wh + (size_t)rB * K_DIM + k0 + cB);
        asm volatile("cp.async.commit_group;" ::: "memory");
    };

    // ldmatrix per-lane base offsets (bytes) within a tile
    const uint32_t lrow = (uint32_t)(lid & 15);
    const uint32_t lchk = (uint32_t)(lid >> 4) * 16;
    const uint32_t aoff = (uint32_t)(m0 + lrow) * ROW_B + lchk;
    const uint32_t boff = (uint32_t)(n0 + lrow) * ROW_B + lchk;

    float acc[2][4][4];
#pragma unroll
    for (int mt = 0; mt < 2; mt++)
#pragma unroll
        for (int nt = 0; nt < 4; nt++)
#pragma unroll
            for (int q = 0; q < 4; q++) acc[mt][nt][q] = 0.0f;

    // Prologue: fill 3 stages
    load_stage(0, 0);
    load_stage(1, 1);
    load_stage(2, 2);

#pragma unroll 1
    for (int kt = 0; kt < KT; kt++) {
        asm volatile("cp.async.wait_group 2;" ::: "memory");
        __syncthreads();

        // Refill stage (kt+3); its slot was consumed at iter kt-1 (guarded by
        // the barrier above). Always commit so wait_group accounting stays 1:1.
        if (kt + 3 < KT) load_stage((kt + 3) & 3, kt + 3);
        else asm volatile("cp.async.commit_group;" ::: "memory");

        const uint32_t sba = dynbase + (kt & 3) * STAGE_B;
        const uint32_t sbb = sba + TILE_A;

#pragma unroll
        for (int ks = 0; ks < 2; ks++) {
            const uint32_t kb = (uint32_t)(ks * 32);   // 16 halves = 32B

            uint32_t A[2][4];
#pragma unroll
            for (int mt = 0; mt < 2; mt++)
                ldsm4(A[mt], sba + aoff + mt * (16 * ROW_B) + kb);

#pragma unroll
            for (int nt2 = 0; nt2 < 2; nt2++) {
                uint32_t r[4];
                ldsm4(r, sbb + boff + nt2 * (16 * ROW_B) + kb);
#pragma unroll
                for (int mt = 0; mt < 2; mt++) {
                    mma_f16(acc[mt][nt2 * 2],     A[mt], r[0], r[2]);
                    mma_f16(acc[mt][nt2 * 2 + 1], A[mt], r[1], r[3]);
                }
            }
        }
    }

    // Epilogue: add bias, store float2 per fragment half.
    const int cq = (lid & 3) * 2;       // col pair within n8 tile
    const int cr = lid >> 2;            // row within m16 tile (0..7)
    const float* bp = bias + bn * 64 + n0;

    float2 bv[4];
#pragma unroll
    for (int nt = 0; nt < 4; nt++)
        bv[nt] = *reinterpret_cast<const float2*>(bp + nt * 8 + cq);

#pragma unroll
    for (int mt = 0; mt < 2; mt++) {
        const int row_g = bm * 128 + m0 + mt * 16 + cr;
        float* orow = out + (size_t)row_g * N_DIM + bn * 64 + n0;
#pragma unroll
        for (int nt = 0; nt < 4; nt++) {
            float2 v0, v1;
            v0.x = acc[mt][nt][0] + bv[nt].x;
            v0.y = acc[mt][nt][1] + bv[nt].y;
            v1.x = acc[mt][nt][2] + bv[nt].x;
            v1.y = acc[mt][nt][3] + bv[nt].y;
            *reinterpret_cast<float2*>(orow + nt * 8 + cq) = v0;
            *reinterpret_cast<float2*>(orow + (size_t)8 * N_DIM + nt * 8 + cq) = v1;
        }
    }
}

// ---------------------------------------------------------------------------
// kernel_launch: fused fp16 convert, then single-product HMMA GEMM.
// Graph-capturable (kernel launches only).
// ---------------------------------------------------------------------------
extern "C" void kernel_launch(void* const* d_in, const int* in_sizes, int n_in,
                              void* d_out, int out_size) {
    const float* x    = (const float*)d_in[0];   // [4096, 2048]
    const float* w    = (const float*)d_in[1];   // [2048, 2048]
    const float* bias = (const float*)d_in[2];   // [2048]
    float* out = (float*)d_out;                  // [4096, 2048]

    (void)in_sizes; (void)n_in; (void)out_size;

    cvt_kernel<<<CVT_THREADS / 256, 256>>>(x, w);

    static bool attr_set = false;
    if (!attr_set) {
        cudaFuncSetAttribute(gemm_kernel,
                             cudaFuncAttributeMaxDynamicSharedMemorySize, SMEM_DYN);
        attr_set = true;
    }
    dim3 grid(N_DIM / 64, M_DIM / 128);   // (32, 32) = 1024 CTAs
    gemm_kernel<<<grid, 256, SMEM_DYN>>>(bias, out);
}